// round 8
// baseline (speedup 1.0000x reference)
#include <cuda_runtime.h>

#define BB 64
#define NN 2048
#define MM 256
#define CHUNKS 32                        // partial chunks per batch
#define ROWS_PER_BLOCK (NN / CHUNKS)     // 64 rows per block

// ---- scratch (static __device__ globals; no allocation) ----
__device__ float  g_partial[CHUNKS * BB * MM];   // chunk-major partials, 2 MB
__device__ float2 g_scal[CHUNKS * BB];           // (sum u, sum u*ww) per chunk
__device__ int    g_count[BB];                   // arrival counters (self-resetting)

// ============================================================================
// Single kernel: streaming pass over memory (read ONCE) + fenced tail reduce.
//
// Block (b, chunk) handles 64 rows. Per row pair (warp-cooperative, 2 rows in
// flight so the two butterfly chains interleave):
//   dot = <row, k>, ss = <row, row>  via butterfly shuffle
//   u = exp( dot / (||row||*||k||) )   [cos in [-1,1] -> no max subtraction]
//   acc += u * (1 - wlu_prev[n]) * row [row still in registers]
//   U += u ;  W += u * ww[n]
// Epilogue: publish partial; 32nd-arriving block per batch sums the 32
// partials in FIXED index order (deterministic) and writes out.
// grid = BB*CHUNKS = 2048 blocks, block = 256 (8 warps x 8 rows each).
// ============================================================================
__global__ void k_fused(const float* __restrict__ mem, const float* __restrict__ k,
                        const float* __restrict__ g,   const float* __restrict__ w_prev,
                        const int* __restrict__ w_lu_prev, float* __restrict__ out)
{
    const int bid   = blockIdx.x;
    const int b     = bid >> 5;          // / CHUNKS
    const int chunk = bid & (CHUNKS - 1);
    const int row0  = chunk * ROWS_PER_BLOCK;
    const int t     = threadIdx.x;
    const int warp  = t >> 5, lane = t & 31;

    __shared__ float4 sk4[MM / 4];           // k[b,:]
    __shared__ float  s_mask[ROWS_PER_BLOCK];
    __shared__ float  s_ww[ROWS_PER_BLOCK];
    __shared__ float  s_red[8];
    __shared__ float  s_kinv;

    // ---- k into smem + ||k|| ----
    if (t < MM / 4) sk4[t] = reinterpret_cast<const float4*>(k + (size_t)b * MM)[t];
    float kv = k[(size_t)b * MM + t];
    float ks = kv * kv;
    #pragma unroll
    for (int off = 16; off > 0; off >>= 1) ks += __shfl_down_sync(0xffffffffu, ks, off);
    if (lane == 0) s_red[warp] = ks;

    // ---- per-row mask / ww coefficients ----
    const float gb = g[b];
    if (t < ROWS_PER_BLOCK) {
        int n = row0 + t;
        float wlu = (float)w_lu_prev[(size_t)b * NN + n];
        float wrp = w_prev[((size_t)b * 2 + 1) * NN + n];    // w_prev[:,1,:]
        s_mask[t] = 1.f - wlu;
        s_ww[t]   = gb * wrp + (1.f - gb) * wlu;
    }
    __syncthreads();
    if (t == 0) {
        float r = s_red[0];
        #pragma unroll
        for (int i = 1; i < 8; i++) r += s_red[i];
        s_kinv = 1.f / fmaxf(sqrtf(r), 1e-8f);
    }
    __syncthreads();

    const float  kinv = s_kinv;
    const float4 k0 = sk4[lane], k1 = sk4[lane + 32];
    const float4* base = reinterpret_cast<const float4*>(
        mem + ((size_t)b * NN + row0) * MM);

    float4 acc0 = make_float4(0.f, 0.f, 0.f, 0.f);
    float4 acc1 = make_float4(0.f, 0.f, 0.f, 0.f);
    float  U = 0.f, W = 0.f;

    // ---- main loop: 4 pairs of rows per warp ----
    #pragma unroll
    for (int p = 0; p < 4; p++) {
        const int ra = warp * 8 + p * 2;
        const int rb = ra + 1;
        float4 a0 = base[(size_t)ra * (MM / 4) + lane];
        float4 a1 = base[(size_t)ra * (MM / 4) + lane + 32];
        float4 b0 = base[(size_t)rb * (MM / 4) + lane];
        float4 b1 = base[(size_t)rb * (MM / 4) + lane + 32];

        float dA = a0.x * k0.x + a0.y * k0.y + a0.z * k0.z + a0.w * k0.w
                 + a1.x * k1.x + a1.y * k1.y + a1.z * k1.z + a1.w * k1.w;
        float sA = a0.x * a0.x + a0.y * a0.y + a0.z * a0.z + a0.w * a0.w
                 + a1.x * a1.x + a1.y * a1.y + a1.z * a1.z + a1.w * a1.w;
        float dB = b0.x * k0.x + b0.y * k0.y + b0.z * k0.z + b0.w * k0.w
                 + b1.x * k1.x + b1.y * k1.y + b1.z * k1.z + b1.w * k1.w;
        float sB = b0.x * b0.x + b0.y * b0.y + b0.z * b0.z + b0.w * b0.w
                 + b1.x * b1.x + b1.y * b1.y + b1.z * b1.z + b1.w * b1.w;

        // two independent butterfly chains, interleaved -> latency overlapped
        #pragma unroll
        for (int off = 16; off > 0; off >>= 1) {
            dA += __shfl_xor_sync(0xffffffffu, dA, off);
            dB += __shfl_xor_sync(0xffffffffu, dB, off);
            sA += __shfl_xor_sync(0xffffffffu, sA, off);
            sB += __shfl_xor_sync(0xffffffffu, sB, off);
        }

        float uA = __expf(dA * kinv * rsqrtf(fmaxf(sA, 1e-16f)));
        float uB = __expf(dB * kinv * rsqrtf(fmaxf(sB, 1e-16f)));
        float cA = uA * s_mask[ra];
        float cB = uB * s_mask[rb];

        acc0.x += cA * a0.x + cB * b0.x;  acc0.y += cA * a0.y + cB * b0.y;
        acc0.z += cA * a0.z + cB * b0.z;  acc0.w += cA * a0.w + cB * b0.w;
        acc1.x += cA * a1.x + cB * b1.x;  acc1.y += cA * a1.y + cB * b1.y;
        acc1.z += cA * a1.z + cB * b1.z;  acc1.w += cA * a1.w + cB * b1.w;
        if (lane == 0) { U += uA + uB; W += uA * s_ww[ra] + uB * s_ww[rb]; }
    }

    // ---- block epilogue: reduce 8 warp accumulators, publish partial ----
    __shared__ float4 red0[8][32];
    __shared__ float4 red1[8][32];
    __shared__ float  sU[8], sW[8];
    red0[warp][lane] = acc0;
    red1[warp][lane] = acc1;
    if (lane == 0) { sU[warp] = U; sW[warp] = W; }
    __syncthreads();

    if (t < 64) {
        float4 s = make_float4(0.f, 0.f, 0.f, 0.f);
        #pragma unroll
        for (int w = 0; w < 8; w++) {
            float4 a = (t < 32) ? red0[w][t] : red1[w][t - 32];
            s.x += a.x; s.y += a.y; s.z += a.z; s.w += a.w;
        }
        reinterpret_cast<float4*>(
            g_partial + ((size_t)chunk * BB + b) * MM)[t] = s;
    }
    if (t == 0) {
        float Ut = sU[0], Wt = sW[0];
        #pragma unroll
        for (int w = 1; w < 8; w++) { Ut += sU[w]; Wt += sW[w]; }
        g_scal[(size_t)chunk * BB + b] = make_float2(Ut, Wt);
    }

    // ---- fenced tail reduce: 32nd-arriving block per batch finishes b ----
    __shared__ int s_last;
    __threadfence();                 // make this block's partial globally visible
    __syncthreads();                 // partial writes done before counting
    if (t == 0) s_last = (atomicAdd(&g_count[b], 1) == CHUNKS - 1) ? 1 : 0;
    __syncthreads();
    if (!s_last) return;

    __threadfence();                 // see all other blocks' partials

    // 256 threads, one output column each; fixed-order sum -> deterministic
    float acc = 0.f;
    #pragma unroll
    for (int c = 0; c < CHUNKS; c++)
        acc += g_partial[((size_t)c * BB + b) * MM + t];

    __shared__ float s_Ut, s_Wt;
    if (t < 32) {
        float2 sc = g_scal[(size_t)t * BB + b];
        float u = sc.x, w = sc.y;
        #pragma unroll
        for (int off = 16; off > 0; off >>= 1) {
            u += __shfl_down_sync(0xffffffffu, u, off);
            w += __shfl_down_sync(0xffffffffu, w, off);
        }
        if (t == 0) { s_Ut = u; s_Wt = w; g_count[b] = 0; }   // reset for replay
    }
    __syncthreads();

    out[(size_t)b * MM + t] = (acc + s_Wt * k[(size_t)b * MM + t]) / s_Ut;
}

// ============================================================================
extern "C" void kernel_launch(void* const* d_in, const int* in_sizes, int n_in,
                              void* d_out, int out_size)
{
    const float* mem       = (const float*)d_in[0];   // (64,2048,256) f32
    const float* k         = (const float*)d_in[1];   // (64,256) f32
    const float* g         = (const float*)d_in[2];   // (64,1) f32
    // d_in[3] gamma: unused (dead w.r.t. output)
    const float* w_prev    = (const float*)d_in[4];   // (64,2,2048) f32
    const int*   w_lu_prev = (const int*)d_in[5];     // (64,2048) i32
    // d_in[6] n: unused (sort/w_lu are dead w.r.t. output)
    float* out = (float*)d_out;                       // (64,256) f32

    k_fused<<<BB * CHUNKS, 256>>>(mem, k, g, w_prev, w_lu_prev, out);
}

// round 11
// speedup vs baseline: 1.0578x; 1.0578x over previous
#include <cuda_runtime.h>
#include <cstdint>

#define BB 64
#define NN 2048
#define MM 256
#define CHUNKS 32                        // partial chunks per batch
#define ROWS_PER_BLOCK (NN / CHUNKS)     // 64 rows per block

// ---- scratch (static __device__ globals; no allocation) ----
__device__ float  g_partial[CHUNKS * BB * MM];   // chunk-major partials, 2 MB
__device__ float2 g_scal[CHUNKS * BB];           // (sum u, sum u*ww) per chunk
__device__ int    g_count[BB];                   // arrival counters (self-resetting)

// ---- cp.async helpers ----
__device__ __forceinline__ void cp_async16(uint32_t smem_dst, const void* gmem_src) {
    asm volatile("cp.async.cg.shared.global [%0], [%1], 16;\n"
                 :: "r"(smem_dst), "l"(gmem_src));
}
__device__ __forceinline__ void cp_commit() {
    asm volatile("cp.async.commit_group;\n");
}
template <int N>
__device__ __forceinline__ void cp_wait() {
    asm volatile("cp.async.wait_group %0;\n" :: "n"(N));
}

// ============================================================================
// Single kernel: streaming pass over memory (read ONCE) + fenced tail reduce.
//
// Intra-warp cp.async pipeline: each warp owns 8 rows, staged through a
// 2-buffer ring (2 rows = 2KB per buffer). cp.async bypasses the register
// file, so the warp issues the NEXT pair's loads while computing the current
// pair (dot/ss partials -> 4 interleaved butterfly chains -> u=exp(cos) ->
// accumulate from smem). Only per-warp syncs -> warps slip freely on top.
//
// Epilogue: publish partial; 32nd-arriving block per batch does a fixed-order
// deterministic reduce and writes out (no second kernel, no launch gap).
// grid = BB*CHUNKS = 2048 blocks, block = 256 (8 warps x 8 rows each).
// ============================================================================
__global__ void __launch_bounds__(256, 4)
k_fused(const float* __restrict__ mem, const float* __restrict__ k,
        const float* __restrict__ g,   const float* __restrict__ w_prev,
        const int* __restrict__ w_lu_prev, float* __restrict__ out)
{
    const int bid   = blockIdx.x;
    const int b     = bid >> 5;          // / CHUNKS
    const int chunk = bid & (CHUNKS - 1);
    const int row0  = chunk * ROWS_PER_BLOCK;
    const int t     = threadIdx.x;
    const int warp  = t >> 5, lane = t & 31;

    __shared__ float4 s_tile[8][2][2 * (MM / 4)];  // warp x buf x 2 rows, 32 KB
    __shared__ float4 sk4[MM / 4];                 // k[b,:]
    __shared__ float  s_mask[ROWS_PER_BLOCK];
    __shared__ float  s_ww[ROWS_PER_BLOCK];
    __shared__ float  s_red[8];
    __shared__ float  s_kinv;

    // ---- prologue: k into smem + ||k||, per-row mask/ww ----
    if (t < MM / 4) sk4[t] = reinterpret_cast<const float4*>(k + (size_t)b * MM)[t];
    float kv = k[(size_t)b * MM + t];
    float ks = kv * kv;
    #pragma unroll
    for (int off = 16; off > 0; off >>= 1) ks += __shfl_down_sync(0xffffffffu, ks, off);
    if (lane == 0) s_red[warp] = ks;

    const float gb = g[b];
    if (t < ROWS_PER_BLOCK) {
        int n = row0 + t;
        float wlu = (float)w_lu_prev[(size_t)b * NN + n];
        float wrp = w_prev[((size_t)b * 2 + 1) * NN + n];    // w_prev[:,1,:]
        s_mask[t] = 1.f - wlu;
        s_ww[t]   = gb * wrp + (1.f - gb) * wlu;
    }
    __syncthreads();
    if (t == 0) {
        float r = s_red[0];
        #pragma unroll
        for (int i = 1; i < 8; i++) r += s_red[i];
        s_kinv = 1.f / fmaxf(sqrtf(r), 1e-8f);
    }
    __syncthreads();

    const float  kinv = s_kinv;
    const float4 k0 = sk4[lane], k1 = sk4[lane + 32];
    const float4* gwarp = reinterpret_cast<const float4*>(
        mem + ((size_t)b * NN + row0 + warp * 8) * MM);   // this warp's 8 rows

    const uint32_t tile_s =
        (uint32_t)__cvta_generic_to_shared(&s_tile[warp][0][0]);

    float4 acc0 = make_float4(0.f, 0.f, 0.f, 0.f);
    float4 acc1 = make_float4(0.f, 0.f, 0.f, 0.f);
    float  U = 0.f, W = 0.f;

    // ---- pipeline prolog: fill both buffers (pairs 0 and 1) ----
    #pragma unroll
    for (int buf = 0; buf < 2; buf++) {
        #pragma unroll
        for (int j = 0; j < 4; j++) {
            int e = lane + j * 32;                      // 0..127 float4 of pair
            cp_async16(tile_s + (uint32_t)(buf * 128 + e) * 16,
                       gwarp + buf * 128 + e);
        }
        cp_commit();
    }

    // ---- main loop: 4 pairs of rows, depth-2 ring ----
    #pragma unroll
    for (int p = 0; p < 4; p++) {
        if (p < 3) cp_wait<1>(); else cp_wait<0>();
        __syncwarp();
        const int buf = p & 1;
        const float4* tb = s_tile[warp][buf];

        // dot/ss partials for the 2 rows (independent)
        float dot[2], ss[2];
        #pragma unroll
        for (int r = 0; r < 2; r++) {
            float4 v0 = tb[r * (MM / 4) + lane];
            float4 v1 = tb[r * (MM / 4) + lane + 32];
            dot[r] = v0.x * k0.x + v0.y * k0.y + v0.z * k0.z + v0.w * k0.w
                   + v1.x * k1.x + v1.y * k1.y + v1.z * k1.z + v1.w * k1.w;
            ss[r]  = v0.x * v0.x + v0.y * v0.y + v0.z * v0.z + v0.w * v0.w
                   + v1.x * v1.x + v1.y * v1.y + v1.z * v1.z + v1.w * v1.w;
        }
        // 4 interleaved butterfly chains
        #pragma unroll
        for (int off = 16; off > 0; off >>= 1) {
            #pragma unroll
            for (int r = 0; r < 2; r++) {
                dot[r] += __shfl_xor_sync(0xffffffffu, dot[r], off);
                ss[r]  += __shfl_xor_sync(0xffffffffu, ss[r],  off);
            }
        }
        // u, accumulate (smem re-read)
        #pragma unroll
        for (int r = 0; r < 2; r++) {
            const int rl = warp * 8 + p * 2 + r;
            float u = __expf(dot[r] * kinv * rsqrtf(fmaxf(ss[r], 1e-16f)));
            float c = u * s_mask[rl];
            float4 v0 = tb[r * (MM / 4) + lane];
            float4 v1 = tb[r * (MM / 4) + lane + 32];
            acc0.x += c * v0.x; acc0.y += c * v0.y;
            acc0.z += c * v0.z; acc0.w += c * v0.w;
            acc1.x += c * v1.x; acc1.y += c * v1.y;
            acc1.z += c * v1.z; acc1.w += c * v1.w;
            if (lane == 0) { U += u; W += u * s_ww[rl]; }
        }
        __syncwarp();                       // all lanes done reading buf

        // refill this buffer with pair p+2 (overlaps next pair's compute)
        if (p < 2) {
            #pragma unroll
            for (int j = 0; j < 4; j++) {
                int e = lane + j * 32;
                cp_async16(tile_s + (uint32_t)(buf * 128 + e) * 16,
                           gwarp + (p + 2) * 128 + e);
            }
            cp_commit();
        }
    }

    // ---- block epilogue: reduce 8 warp accumulators, publish partial ----
    __shared__ float4 red0[8][32];
    __shared__ float4 red1[8][32];
    __shared__ float  sU[8], sW[8];
    red0[warp][lane] = acc0;
    red1[warp][lane] = acc1;
    if (lane == 0) { sU[warp] = U; sW[warp] = W; }
    __syncthreads();

    if (t < 64) {
        float4 s = make_float4(0.f, 0.f, 0.f, 0.f);
        #pragma unroll
        for (int w = 0; w < 8; w++) {
            float4 a = (t < 32) ? red0[w][t] : red1[w][t - 32];
            s.x += a.x; s.y += a.y; s.z += a.z; s.w += a.w;
        }
        reinterpret_cast<float4*>(
            g_partial + ((size_t)chunk * BB + b) * MM)[t] = s;
    }
    if (t == 0) {
        float Ut = sU[0], Wt = sW[0];
        #pragma unroll
        for (int w = 1; w < 8; w++) { Ut += sU[w]; Wt += sW[w]; }
        g_scal[(size_t)chunk * BB + b] = make_float2(Ut, Wt);
    }

    // ---- fenced tail reduce: 32nd-arriving block per batch finishes b ----
    __shared__ int s_last;
    __threadfence();                 // make this block's partial globally visible
    __syncthreads();                 // partial writes done before counting
    if (t == 0) s_last = (atomicAdd(&g_count[b], 1) == CHUNKS - 1) ? 1 : 0;
    __syncthreads();
    if (!s_last) return;

    __threadfence();                 // see all other blocks' partials

    // 256 threads, one output column each; fixed-order sum -> deterministic
    float acc = 0.f;
    #pragma unroll
    for (int c = 0; c < CHUNKS; c++)
        acc += g_partial[((size_t)c * BB + b) * MM + t];

    __shared__ float s_Ut, s_Wt;
    if (t < 32) {
        float2 sc = g_scal[(size_t)t * BB + b];
        float u = sc.x, w = sc.y;
        #pragma unroll
        for (int off = 16; off > 0; off >>= 1) {
            u += __shfl_down_sync(0xffffffffu, u, off);
            w += __shfl_down_sync(0xffffffffu, w, off);
        }
        if (t == 0) { s_Ut = u; s_Wt = w; g_count[b] = 0; }   // reset for replay
    }
    __syncthreads();

    out[(size_t)b * MM + t] = (acc + s_Wt * k[(size_t)b * MM + t]) / s_Ut;
}

// ============================================================================
extern "C" void kernel_launch(void* const* d_in, const int* in_sizes, int n_in,
                              void* d_out, int out_size)
{
    const float* mem       = (const float*)d_in[0];   // (64,2048,256) f32
    const float* k         = (const float*)d_in[1];   // (64,256) f32
    const float* g         = (const float*)d_in[2];   // (64,1) f32
    // d_in[3] gamma: unused (dead w.r.t. output)
    const float* w_prev    = (const float*)d_in[4];   // (64,2,2048) f32
    const int*   w_lu_prev = (const int*)d_in[5];     // (64,2048) i32
    // d_in[6] n: unused (sort/w_lu are dead w.r.t. output)
    float* out = (float*)d_out;                       // (64,256) f32

    k_fused<<<BB * CHUNKS, 256>>>(mem, k, g, w_prev, w_lu_prev, out);
}